// round 8
// baseline (speedup 1.0000x reference)
#include <cuda_runtime.h>
#include <math.h>

#define BB 64
#define QQ 900
#define GG 100
#define NC 10
#define NC1 11
#define SLOTS 29   // ceil(900/32)

// -------- device scratch (static: no allocation) --------
__device__ float  g_costT[BB * GG * QQ];             // transposed cost: [b][k][q]
__device__ unsigned long long g_rowpack[BB * GG];    // packed (fkey(minval), argmin q)
__device__ int    g_vlist[BB * GG];
__device__ int    g_nvalid[BB];
__device__ int    g_match[BB * QQ];
__device__ int    g_nmatched;
__device__ int    g_loss_done;
__device__ double g_cls_num;
__device__ double g_cls_den;
__device__ double g_l1;
__device__ double g_gl;

// ordered-uint key: monotone map float -> uint32 (handles negatives)
__device__ __forceinline__ unsigned int fkey(float f) {
    unsigned int b = __float_as_uint(f);
    return (b & 0x80000000u) ? ~b : (b | 0x80000000u);
}
__device__ __forceinline__ float fkey_inv(unsigned int key) {
    unsigned int b = (key & 0x80000000u) ? (key ^ 0x80000000u) : ~key;
    return __uint_as_float(b);
}

// one block per batch: compact valid gt indices, init rowpack + accumulators
__global__ void prep_kernel(const int* __restrict__ gt_classes) {
    int b = blockIdx.x;
    for (int k = threadIdx.x; k < GG; k += blockDim.x)
        g_rowpack[b * GG + k] = 0xFFFFFFFFFFFFFFFFull;
    if (threadIdx.x == 0) {
        if (b == 0) {
            g_nmatched = 0;
            g_loss_done = 0;
            g_cls_num = 0.0;
            g_cls_den = 0.0;
            g_l1 = 0.0;
            g_gl = 0.0;
        }
        int n = 0;
        for (int g = 0; g < GG; g++) {
            if (gt_classes[b * GG + g] >= 0) g_vlist[b * GG + n++] = g;
        }
        g_nvalid[b] = n;
    }
}

// cost[b][q][k] -> g_costT[(b*GG + k)*QQ + q]; fused per-row (min, argmin)
// via packed-key warp reduce + atomicMin (bit-identical to a separate pass:
// min value, ties -> smallest q).
__global__ void cost_kernel(const float* __restrict__ logits,
                            const float* __restrict__ pboxes,
                            const int*   __restrict__ gtc,
                            const float* __restrict__ gboxes) {
    int b = blockIdx.y;
    int q = blockIdx.x * blockDim.x + threadIdx.x;
    const bool valid = q < QQ;
    const int qc = valid ? q : QQ - 1;
    const int lane = threadIdx.x & 31;

    __shared__ float sgx0[GG], sgy0[GG], sgx1[GG], sgy1[GG], sga[GG];
    __shared__ float sgcx[GG], sgcy[GG], sgw[GG], sgh[GG];
    __shared__ int   scls[GG];
    __shared__ int   sn;

    if (threadIdx.x == 0) sn = g_nvalid[b];
    __syncthreads();
    int n = sn;

    for (int k = threadIdx.x; k < n; k += blockDim.x) {
        int gi = g_vlist[b * GG + k];
        const float* gb = gboxes + ((size_t)(b * GG + gi)) * 4;
        float cx = gb[0], cy = gb[1], w = gb[2], h = gb[3];
        float x0 = cx - w * 0.5f, y0 = cy - h * 0.5f;
        float x1 = cx + w * 0.5f, y1 = cy + h * 0.5f;
        sgx0[k] = x0; sgy0[k] = y0; sgx1[k] = x1; sgy1[k] = y1;
        sga[k] = fmaxf(x1 - x0, 0.f) * fmaxf(y1 - y0, 0.f);
        sgcx[k] = cx; sgcy[k] = cy; sgw[k] = w; sgh[k] = h;
        int c = gtc[b * GG + gi];
        scls[k] = (c < 0) ? 0 : (c > NC - 1 ? NC - 1 : c);
    }
    __syncthreads();

    // softmax over NC1 logits
    const float* lg = logits + ((size_t)(b * QQ + qc)) * NC1;
    float e[NC1];
    float mx = lg[0];
#pragma unroll
    for (int c = 1; c < NC1; c++) mx = fmaxf(mx, lg[c]);
    float s = 0.f;
#pragma unroll
    for (int c = 0; c < NC1; c++) { e[c] = expf(lg[c] - mx); s += e[c]; }
    float inv_s = 1.0f / s;

    const float* pb = pboxes + ((size_t)(b * QQ + qc)) * 4;
    float pcx = pb[0], pcy = pb[1], pw = pb[2], ph = pb[3];
    float px0 = pcx - pw * 0.5f, py0 = pcy - ph * 0.5f;
    float px1 = pcx + pw * 0.5f, py1 = pcy + ph * 0.5f;
    float pa = fmaxf(px1 - px0, 0.f) * fmaxf(py1 - py0, 0.f);

    float* outc = g_costT + (size_t)b * GG * QQ + q;
    for (int k = 0; k < n; k++) {
        float clsc = -(e[scls[k]] * inv_s);
        float l1 = fabsf(pcx - sgcx[k]) + fabsf(pcy - sgcy[k]) +
                   fabsf(pw - sgw[k]) + fabsf(ph - sgh[k]);
        float gx0 = sgx0[k], gy0 = sgy0[k], gx1 = sgx1[k], gy1 = sgy1[k];
        float ltx = fmaxf(px0, gx0), lty = fmaxf(py0, gy0);
        float rbx = fminf(px1, gx1), rby = fminf(py1, gy1);
        float iw = fmaxf(rbx - ltx, 0.f), ih = fmaxf(rby - lty, 0.f);
        float inter = iw * ih;
        float uni = pa + sga[k] - inter;
        float iou = inter / fmaxf(uni, 1e-6f);
        float ex0 = fminf(px0, gx0), ey0 = fminf(py0, gy0);
        float ex1 = fmaxf(px1, gx1), ey1 = fmaxf(py1, gy1);
        float ew = fmaxf(ex1 - ex0, 0.f), eh = fmaxf(ey1 - ey0, 0.f);
        float enc = ew * eh;
        float giou = iou - (enc - uni) / fmaxf(enc, 1e-6f);
        float cval = 2.0f * clsc + 5.0f * l1 - 2.0f * giou;
        if (valid) outc[(size_t)k * QQ] = cval;

        unsigned long long pk = valid
            ? (((unsigned long long)fkey(cval) << 32) | (unsigned int)q)
            : 0xFFFFFFFFFFFFFFFFull;
#pragma unroll
        for (int off = 16; off; off >>= 1) {
            unsigned long long o = __shfl_down_sync(0xffffffffu, pk, off);
            if (o < pk) pk = o;
        }
        if (lane == 0) atomicMin(&g_rowpack[b * GG + k], pk);
    }
}

// Warm-started Jonker-Volgenant, 1 warp per batch, float32 duals (v=0 start;
// the fp32-safe variant that matched the reference exactly in R4/R5).
//  init: u[i] = row min, greedy-assign rows at their argmin column if free
//  (reduced cost exactly 0 -> CS holds). Remaining free rows solved by exact
//  shortest-augmenting-path with cumulative-offset duals.
__global__ void __launch_bounds__(32) jv_kernel() {
    const int b = blockIdx.x;
    const int lane = threadIdx.x;
    const int m = QQ;
    const int n = g_nvalid[b];
    const float FNAN = __int_as_float(0x7fc00000);

    __shared__ float2 svm[QQ + 1];   // .x = committed v dual, .y = minv'
    __shared__ float  su[GG + 2];    // committed u duals
    __shared__ float  sDused[QQ + 1];
    __shared__ int    sway[QQ + 1];
    __shared__ int    sp[QQ + 1];
    __shared__ int    susedList[QQ + 1];
    __shared__ int    sfree[GG + 1];
    __shared__ unsigned long long srowpk[GG];
    __shared__ int    snfree;

    for (int j = lane; j <= m; j += 32) { svm[j] = make_float2(0.f, 1e30f); sp[j] = 0; }
    for (int i = lane; i < GG + 2; i += 32) su[i] = 0.0f;
    for (int i = lane; i < n; i += 32) srowpk[i] = g_rowpack[b * GG + i];
    __syncwarp();

    // row reduction + greedy assignment (decisions serial, data from LDS)
    if (lane == 0) {
        int nf = 0;
        for (int i = 1; i <= n; i++) {
            unsigned long long pk = srowpk[i - 1];
            su[i] = fkey_inv((unsigned int)(pk >> 32));
            int jmin = (int)(pk & 0xFFFFFFFFull) + 1;
            if (sp[jmin] == 0) sp[jmin] = i;
            else sfree[nf++] = i;
        }
        snfree = nf;
    }
    __syncwarp();
    const int nfree = snfree;

    const float* Cbase = g_costT + (size_t)b * GG * QQ;

    for (int fi = 0; fi < nfree; fi++) {
        const int i = sfree[fi];
        // reset minv' for owned columns (v persists)
#pragma unroll
        for (int s = 0; s < SLOTS; s++) {
            int j = 1 + lane + (s << 5);
            if (j <= m) svm[j].y = 1e30f;
        }
        if (lane == 0) sp[0] = i;
        __syncwarp();

        int j0 = 0;       // uniform across warp
        float D = 0.0f;
        int cnt = 0;

        while (true) {
            const int i0 = sp[j0];            // uniform LDS broadcast
            const float ueff = su[i0] - D;
            if (lane == 0) { susedList[cnt] = j0; sDused[cnt] = D; }
            if (j0 > 0 && (((j0 - 1) & 31) == lane)) svm[j0].y = FNAN; // mark used
            cnt++;

            const float* __restrict__ Crow = Cbase + (size_t)(i0 - 1) * QQ;

            // batched loads: full MLP, one L2 round trip
            float c[SLOTS];
#pragma unroll
            for (int s = 0; s < SLOTS; s++) {
                int j = 1 + lane + (s << 5);
                c[s] = (j <= m) ? __ldg(&Crow[j - 1]) : 1e30f;
            }

            // compute pass against owned shared state (R5 float order)
            float lmin = 1e30f;
            int lj = m + 1;
#pragma unroll
            for (int s = 0; s < SLOTS; s++) {
                int j = 1 + lane + (s << 5);
                if (j <= m) {
                    float2 vm = svm[j];
                    float cur = c[s] - ueff - vm.x;
                    float mv = vm.y;               // NaN if used
                    if (cur < mv) {                 // false when mv is NaN
                        mv = cur;
                        svm[j].y = cur;
                        sway[j] = j0;
                    }
                    if (mv < lmin) { lmin = mv; lj = j; }  // false when NaN
                }
            }
            // warp (value, index) min-reduce; tie -> smaller index
#pragma unroll
            for (int off = 16; off; off >>= 1) {
                float ov = __shfl_down_sync(0xffffffffu, lmin, off);
                int   oi = __shfl_down_sync(0xffffffffu, lj, off);
                if (ov < lmin || (ov == lmin && oi < lj)) { lmin = ov; lj = oi; }
            }
            D  = __shfl_sync(0xffffffffu, lmin, 0);  // new cumulative offset
            j0 = __shfl_sync(0xffffffffu, lj, 0);
            if (sp[j0] == 0) break;
        }

        // commit duals over used columns (distinct rows & cols -> race-free)
        __syncwarp();
        for (int t = lane; t < cnt; t += 32) {
            int j = susedList[t];
            float dd = D - sDused[t];
            su[sp[j]] += dd;
            if (j != 0) svm[j].x -= dd;
        }
        __syncwarp();
        if (lane == 0) {
            int jj = j0;
            while (jj != 0) {
                int jn = sway[jj];
                sp[jj] = sp[jn];
                jj = jn;
            }
        }
        __syncwarp();
    }

    for (int j = lane + 1; j <= m; j += 32) {
        int r = sp[j];
        g_match[b * QQ + (j - 1)] = (r > 0) ? g_vlist[b * GG + (r - 1)] : -1;
    }
    if (lane == 0) atomicAdd(&g_nmatched, n);
}

__global__ void loss_kernel(const float* __restrict__ logits,
                            const float* __restrict__ pboxes,
                            const int*   __restrict__ gtc,
                            const float* __restrict__ gboxes,
                            float* __restrict__ out) {
    int idx = blockIdx.x * blockDim.x + threadIdx.x;
    double nllw = 0.0, wsum = 0.0, l1acc = 0.0, glacc = 0.0;

    if (idx < BB * QQ) {
        int b = idx / QQ;
        const float* lg = logits + (size_t)idx * NC1;
        float mx = lg[0];
#pragma unroll
        for (int c = 1; c < NC1; c++) mx = fmaxf(mx, lg[c]);
        float s = 0.f;
#pragma unroll
        for (int c = 0; c < NC1; c++) s += expf(lg[c] - mx);
        float logZ = mx + logf(s);

        int mg = g_match[idx];
        int t = (mg >= 0) ? gtc[b * GG + mg] : NC;
        float logp = lg[t] - logZ;
        float wt = (t == NC) ? 0.1f : 1.0f;
        nllw = (double)(wt * (-logp));
        wsum = (double)wt;

        if (mg >= 0) {
            const float* pb = pboxes + (size_t)idx * 4;
            const float* gb = gboxes + ((size_t)(b * GG + mg)) * 4;
            float pcx = pb[0], pcy = pb[1], pw = pb[2], ph = pb[3];
            float gcx = gb[0], gcy = gb[1], gw = gb[2], gh = gb[3];
            l1acc = (double)(fabsf(pcx - gcx) + fabsf(pcy - gcy) +
                             fabsf(pw - gw) + fabsf(ph - gh));
            float px0 = pcx - pw * 0.5f, py0 = pcy - ph * 0.5f;
            float px1 = pcx + pw * 0.5f, py1 = pcy + ph * 0.5f;
            float gx0 = gcx - gw * 0.5f, gy0 = gcy - gh * 0.5f;
            float gx1 = gcx + gw * 0.5f, gy1 = gcy + gh * 0.5f;
            float pa = fmaxf(px1 - px0, 0.f) * fmaxf(py1 - py0, 0.f);
            float ga = fmaxf(gx1 - gx0, 0.f) * fmaxf(gy1 - gy0, 0.f);
            float ltx = fmaxf(px0, gx0), lty = fmaxf(py0, gy0);
            float rbx = fminf(px1, gx1), rby = fminf(py1, gy1);
            float iw = fmaxf(rbx - ltx, 0.f), ih = fmaxf(rby - lty, 0.f);
            float inter = iw * ih;
            float uni = pa + ga - inter;
            float iou = inter / fmaxf(uni, 1e-6f);
            float ex0 = fminf(px0, gx0), ey0 = fminf(py0, gy0);
            float ex1 = fmaxf(px1, gx1), ey1 = fmaxf(py1, gy1);
            float ew = fmaxf(ex1 - ex0, 0.f), eh = fmaxf(ey1 - ey0, 0.f);
            float enc = ew * eh;
            float giou = iou - (enc - uni) / fmaxf(enc, 1e-6f);
            glacc = (double)(1.0f - giou);
        }
    }

    __shared__ double s1[256], s2[256], s3[256], s4[256];
    int tid = threadIdx.x;
    s1[tid] = nllw; s2[tid] = wsum; s3[tid] = l1acc; s4[tid] = glacc;
    __syncthreads();
#pragma unroll
    for (int s = 128; s > 0; s >>= 1) {
        if (tid < s) {
            s1[tid] += s1[tid + s];
            s2[tid] += s2[tid + s];
            s3[tid] += s3[tid + s];
            s4[tid] += s4[tid + s];
        }
        __syncthreads();
    }
    if (tid == 0) {
        atomicAdd(&g_cls_num, s1[0]);
        atomicAdd(&g_cls_den, s2[0]);
        atomicAdd(&g_l1, s3[0]);
        atomicAdd(&g_gl, s4[0]);
        __threadfence();
        int done = atomicAdd(&g_loss_done, 1);
        if (done == gridDim.x - 1) {   // last block finalizes
            int nm = g_nmatched;
            if (nm < 1) nm = 1;
            double nmd = (double)nm;
            double cls = g_cls_num / g_cls_den;
            out[0] = (float)(2.0 * cls + 5.0 * g_l1 / nmd + 2.0 * g_gl / nmd);
        }
    }
}

extern "C" void kernel_launch(void* const* d_in, const int* in_sizes, int n_in,
                              void* d_out, int out_size) {
    const float* pred_logits = (const float*)d_in[0];
    const float* pred_boxes  = (const float*)d_in[1];
    const int*   gt_classes  = (const int*)d_in[2];
    const float* gt_boxes    = (const float*)d_in[3];
    float* out = (float*)d_out;

    prep_kernel<<<BB, 128>>>(gt_classes);

    dim3 cgrid((QQ + 127) / 128, BB);
    cost_kernel<<<cgrid, 128>>>(pred_logits, pred_boxes, gt_classes, gt_boxes);

    jv_kernel<<<BB, 32>>>();

    int total = BB * QQ;
    loss_kernel<<<(total + 255) / 256, 256>>>(pred_logits, pred_boxes,
                                              gt_classes, gt_boxes, out);
}

// round 9
// speedup vs baseline: 1.1291x; 1.1291x over previous
#include <cuda_runtime.h>
#include <math.h>

#define BB 64
#define QQ 900
#define GG 100
#define NC 10
#define NC1 11
#define SLOTS 29   // ceil(900/32)

// -------- device scratch (static: no allocation) --------
__device__ float  g_costT[BB * GG * QQ];   // transposed cost: [b][k][q]
__device__ float  g_logZ[BB * QQ];         // log-partition per (b,q), reused by loss
__device__ int    g_vlist[BB * GG];
__device__ int    g_nvalid[BB];
__device__ float  g_rowminval[BB * GG];
__device__ int    g_rowminidx[BB * GG];
__device__ int    g_match[BB * QQ];
__device__ int    g_nmatched;
__device__ int    g_loss_done;
__device__ double g_cls_num;
__device__ double g_cls_den;
__device__ double g_l1;
__device__ double g_gl;

// ordered-uint key: monotone map float -> uint32 (handles negatives)
__device__ __forceinline__ unsigned int fkey(float f) {
    unsigned int b = __float_as_uint(f);
    return (b & 0x80000000u) ? ~b : (b | 0x80000000u);
}

// one block per batch: compact valid gt indices (+ global init on block 0)
__global__ void prep_kernel(const int* __restrict__ gt_classes) {
    int b = blockIdx.x;
    if (threadIdx.x == 0) {
        if (b == 0) {
            g_nmatched = 0;
            g_loss_done = 0;
            g_cls_num = 0.0;
            g_cls_den = 0.0;
            g_l1 = 0.0;
            g_gl = 0.0;
        }
        int n = 0;
        for (int g = 0; g < GG; g++) {
            if (gt_classes[b * GG + g] >= 0) g_vlist[b * GG + n++] = g;
        }
        g_nvalid[b] = n;
    }
}

// cost[b][q][k] -> g_costT[(b*GG + k)*QQ + q]; also writes logZ per (b,q)
__global__ void cost_kernel(const float* __restrict__ logits,
                            const float* __restrict__ pboxes,
                            const int*   __restrict__ gtc,
                            const float* __restrict__ gboxes) {
    int b = blockIdx.y;
    int q = blockIdx.x * blockDim.x + threadIdx.x;

    __shared__ float sgx0[GG], sgy0[GG], sgx1[GG], sgy1[GG], sga[GG];
    __shared__ float sgcx[GG], sgcy[GG], sgw[GG], sgh[GG];
    __shared__ int   scls[GG];
    __shared__ int   sn;

    if (threadIdx.x == 0) sn = g_nvalid[b];
    __syncthreads();
    int n = sn;

    for (int k = threadIdx.x; k < n; k += blockDim.x) {
        int gi = g_vlist[b * GG + k];
        const float* gb = gboxes + ((size_t)(b * GG + gi)) * 4;
        float cx = gb[0], cy = gb[1], w = gb[2], h = gb[3];
        float x0 = cx - w * 0.5f, y0 = cy - h * 0.5f;
        float x1 = cx + w * 0.5f, y1 = cy + h * 0.5f;
        sgx0[k] = x0; sgy0[k] = y0; sgx1[k] = x1; sgy1[k] = y1;
        sga[k] = fmaxf(x1 - x0, 0.f) * fmaxf(y1 - y0, 0.f);
        sgcx[k] = cx; sgcy[k] = cy; sgw[k] = w; sgh[k] = h;
        int c = gtc[b * GG + gi];
        scls[k] = (c < 0) ? 0 : (c > NC - 1 ? NC - 1 : c);
    }
    __syncthreads();
    if (q >= QQ) return;

    // softmax over NC1 logits
    const float* lg = logits + ((size_t)(b * QQ + q)) * NC1;
    float e[NC1];
    float mx = lg[0];
#pragma unroll
    for (int c = 1; c < NC1; c++) mx = fmaxf(mx, lg[c]);
    float s = 0.f;
#pragma unroll
    for (int c = 0; c < NC1; c++) { e[c] = expf(lg[c] - mx); s += e[c]; }
    float inv_s = 1.0f / s;
    g_logZ[b * QQ + q] = mx + logf(s);   // reused by loss_kernel

    const float* pb = pboxes + ((size_t)(b * QQ + q)) * 4;
    float pcx = pb[0], pcy = pb[1], pw = pb[2], ph = pb[3];
    float px0 = pcx - pw * 0.5f, py0 = pcy - ph * 0.5f;
    float px1 = pcx + pw * 0.5f, py1 = pcy + ph * 0.5f;
    float pa = fmaxf(px1 - px0, 0.f) * fmaxf(py1 - py0, 0.f);

    float* outc = g_costT + (size_t)b * GG * QQ + q;
    for (int k = 0; k < n; k++) {
        float clsc = -(e[scls[k]] * inv_s);
        float l1 = fabsf(pcx - sgcx[k]) + fabsf(pcy - sgcy[k]) +
                   fabsf(pw - sgw[k]) + fabsf(ph - sgh[k]);
        float gx0 = sgx0[k], gy0 = sgy0[k], gx1 = sgx1[k], gy1 = sgy1[k];
        float ltx = fmaxf(px0, gx0), lty = fmaxf(py0, gy0);
        float rbx = fminf(px1, gx1), rby = fminf(py1, gy1);
        float iw = fmaxf(rbx - ltx, 0.f), ih = fmaxf(rby - lty, 0.f);
        float inter = iw * ih;
        float uni = pa + sga[k] - inter;
        float iou = inter / fmaxf(uni, 1e-6f);
        float ex0 = fminf(px0, gx0), ey0 = fminf(py0, gy0);
        float ex1 = fmaxf(px1, gx1), ey1 = fmaxf(py1, gy1);
        float ew = fmaxf(ex1 - ex0, 0.f), eh = fmaxf(ey1 - ey0, 0.f);
        float enc = ew * eh;
        float giou = iou - (enc - uni) / fmaxf(enc, 1e-6f);
        outc[(size_t)k * QQ] = 2.0f * clsc + 5.0f * l1 - 2.0f * giou;
    }
}

// one block per (row k, batch b): min+argmin over the 900-entry cost row.
// 900 = 225 float4: threads 0..224 each handle one float4 (q ascending within
// a thread, strict < keeps smallest q); cross-thread ties resolved by packed
// key in the reduce. Result identical to a serial min-with-smallest-index.
__global__ void __launch_bounds__(256) rowmin_kernel() {
    const int k = blockIdx.x;
    const int b = blockIdx.y;
    if (k >= g_nvalid[b]) return;

    const float4* __restrict__ Crow4 =
        (const float4*)(g_costT + ((size_t)(b * GG + k)) * QQ);
    const int tid = threadIdx.x;

    float bestv = 1e30f;
    int bestq = QQ;
    if (tid < 225) {
        float4 v = __ldg(&Crow4[tid]);
        int q0 = tid * 4;
        bestv = v.x; bestq = q0;
        if (v.y < bestv) { bestv = v.y; bestq = q0 + 1; }
        if (v.z < bestv) { bestv = v.z; bestq = q0 + 2; }
        if (v.w < bestv) { bestv = v.w; bestq = q0 + 3; }
    }
    unsigned long long best =
        ((unsigned long long)fkey(bestv) << 32) | (unsigned int)bestq;
#pragma unroll
    for (int off = 16; off; off >>= 1) {
        unsigned long long o = __shfl_down_sync(0xffffffffu, best, off);
        if (o < best) best = o;
    }
    __shared__ unsigned long long sw[8];
    if ((tid & 31) == 0) sw[tid >> 5] = best;
    __syncthreads();
    if (tid == 0) {
        unsigned long long bb = sw[0];
#pragma unroll
        for (int w = 1; w < 8; w++) if (sw[w] < bb) bb = sw[w];
        int q = (int)(bb & 0xFFFFFFFFull);
        g_rowminval[b * GG + k] = ((const float*)Crow4)[q];
        g_rowminidx[b * GG + k] = q;
    }
}

// Warm-started Jonker-Volgenant, 1 warp per batch, float32 duals (v=0 start —
// the fp32-safe variant verified exact in R4/R5/R8).
__global__ void __launch_bounds__(32) jv_kernel() {
    const int b = blockIdx.x;
    const int lane = threadIdx.x;
    const int m = QQ;
    const int n = g_nvalid[b];
    const float FNAN = __int_as_float(0x7fc00000);

    __shared__ float2 svm[QQ + 1];   // .x = committed v dual, .y = minv'
    __shared__ float  su[GG + 2];    // committed u duals
    __shared__ float  sDused[QQ + 1];
    __shared__ int    sway[QQ + 1];
    __shared__ int    sp[QQ + 1];
    __shared__ int    susedList[QQ + 1];
    __shared__ int    sfree[GG + 1];
    __shared__ float  srowval[GG];
    __shared__ int    srowidx[GG];
    __shared__ int    snfree;

    for (int j = lane; j <= m; j += 32) { svm[j] = make_float2(0.f, 1e30f); sp[j] = 0; }
    for (int i = lane; i < GG + 2; i += 32) su[i] = 0.0f;
    for (int i = lane; i < n; i += 32) {
        srowval[i] = g_rowminval[b * GG + i];
        srowidx[i] = g_rowminidx[b * GG + i];
    }
    __syncwarp();

    // row reduction + greedy assignment (decisions serial, data from LDS)
    if (lane == 0) {
        int nf = 0;
        for (int i = 1; i <= n; i++) {
            su[i] = srowval[i - 1];
            int jmin = srowidx[i - 1] + 1;
            if (sp[jmin] == 0) sp[jmin] = i;
            else sfree[nf++] = i;
        }
        snfree = nf;
    }
    __syncwarp();
    const int nfree = snfree;

    const float* Cbase = g_costT + (size_t)b * GG * QQ;

    for (int fi = 0; fi < nfree; fi++) {
        const int i = sfree[fi];
        // reset minv' for owned columns (v persists)
#pragma unroll
        for (int s = 0; s < SLOTS; s++) {
            int j = 1 + lane + (s << 5);
            if (j <= m) svm[j].y = 1e30f;
        }
        if (lane == 0) sp[0] = i;
        __syncwarp();

        int j0 = 0;       // uniform across warp
        float D = 0.0f;
        int cnt = 0;

        while (true) {
            const int i0 = sp[j0];            // uniform LDS broadcast
            const float ueff = su[i0] - D;
            if (lane == 0) { susedList[cnt] = j0; sDused[cnt] = D; }
            if (j0 > 0 && (((j0 - 1) & 31) == lane)) svm[j0].y = FNAN; // mark used
            cnt++;

            const float* __restrict__ Crow = Cbase + (size_t)(i0 - 1) * QQ;

            // batched loads: full MLP, one L2 round trip
            float c[SLOTS];
#pragma unroll
            for (int s = 0; s < SLOTS; s++) {
                int j = 1 + lane + (s << 5);
                c[s] = (j <= m) ? __ldg(&Crow[j - 1]) : 1e30f;
            }

            // compute pass against owned shared state (R5 float order)
            float lmin = 1e30f;
            int lj = m + 1;
#pragma unroll
            for (int s = 0; s < SLOTS; s++) {
                int j = 1 + lane + (s << 5);
                if (j <= m) {
                    float2 vm = svm[j];
                    float cur = c[s] - ueff - vm.x;
                    float mv = vm.y;               // NaN if used
                    if (cur < mv) {                 // false when mv is NaN
                        mv = cur;
                        svm[j].y = cur;
                        sway[j] = j0;
                    }
                    if (mv < lmin) { lmin = mv; lj = j; }  // false when NaN
                }
            }
            // warp (value, index) min-reduce; tie -> smaller index
#pragma unroll
            for (int off = 16; off; off >>= 1) {
                float ov = __shfl_down_sync(0xffffffffu, lmin, off);
                int   oi = __shfl_down_sync(0xffffffffu, lj, off);
                if (ov < lmin || (ov == lmin && oi < lj)) { lmin = ov; lj = oi; }
            }
            D  = __shfl_sync(0xffffffffu, lmin, 0);  // new cumulative offset
            j0 = __shfl_sync(0xffffffffu, lj, 0);
            if (sp[j0] == 0) break;
        }

        // commit duals over used columns (distinct rows & cols -> race-free)
        __syncwarp();
        for (int t = lane; t < cnt; t += 32) {
            int j = susedList[t];
            float dd = D - sDused[t];
            su[sp[j]] += dd;
            if (j != 0) svm[j].x -= dd;
        }
        __syncwarp();
        if (lane == 0) {
            int jj = j0;
            while (jj != 0) {
                int jn = sway[jj];
                sp[jj] = sp[jn];
                jj = jn;
            }
        }
        __syncwarp();
    }

    for (int j = lane + 1; j <= m; j += 32) {
        int r = sp[j];
        g_match[b * QQ + (j - 1)] = (r > 0) ? g_vlist[b * GG + (r - 1)] : -1;
    }
    if (lane == 0) atomicAdd(&g_nmatched, n);
}

__global__ void loss_kernel(const float* __restrict__ logits,
                            const float* __restrict__ pboxes,
                            const int*   __restrict__ gtc,
                            const float* __restrict__ gboxes,
                            float* __restrict__ out) {
    int idx = blockIdx.x * blockDim.x + threadIdx.x;
    double nllw = 0.0, wsum = 0.0, l1acc = 0.0, glacc = 0.0;

    if (idx < BB * QQ) {
        int b = idx / QQ;
        int mg = g_match[idx];
        int t = (mg >= 0) ? gtc[b * GG + mg] : NC;
        float logp = logits[(size_t)idx * NC1 + t] - g_logZ[idx];
        float wt = (t == NC) ? 0.1f : 1.0f;
        nllw = (double)(wt * (-logp));
        wsum = (double)wt;

        if (mg >= 0) {
            const float* pb = pboxes + (size_t)idx * 4;
            const float* gb = gboxes + ((size_t)(b * GG + mg)) * 4;
            float pcx = pb[0], pcy = pb[1], pw = pb[2], ph = pb[3];
            float gcx = gb[0], gcy = gb[1], gw = gb[2], gh = gb[3];
            l1acc = (double)(fabsf(pcx - gcx) + fabsf(pcy - gcy) +
                             fabsf(pw - gw) + fabsf(ph - gh));
            float px0 = pcx - pw * 0.5f, py0 = pcy - ph * 0.5f;
            float px1 = pcx + pw * 0.5f, py1 = pcy + ph * 0.5f;
            float gx0 = gcx - gw * 0.5f, gy0 = gcy - gh * 0.5f;
            float gx1 = gcx + gw * 0.5f, gy1 = gcy + gh * 0.5f;
            float pa = fmaxf(px1 - px0, 0.f) * fmaxf(py1 - py0, 0.f);
            float ga = fmaxf(gx1 - gx0, 0.f) * fmaxf(gy1 - gy0, 0.f);
            float ltx = fmaxf(px0, gx0), lty = fmaxf(py0, gy0);
            float rbx = fminf(px1, gx1), rby = fminf(py1, gy1);
            float iw = fmaxf(rbx - ltx, 0.f), ih = fmaxf(rby - lty, 0.f);
            float inter = iw * ih;
            float uni = pa + ga - inter;
            float iou = inter / fmaxf(uni, 1e-6f);
            float ex0 = fminf(px0, gx0), ey0 = fminf(py0, gy0);
            float ex1 = fmaxf(px1, gx1), ey1 = fmaxf(py1, gy1);
            float ew = fmaxf(ex1 - ex0, 0.f), eh = fmaxf(ey1 - ey0, 0.f);
            float enc = ew * eh;
            float giou = iou - (enc - uni) / fmaxf(enc, 1e-6f);
            glacc = (double)(1.0f - giou);
        }
    }

    __shared__ double s1[256], s2[256], s3[256], s4[256];
    int tid = threadIdx.x;
    s1[tid] = nllw; s2[tid] = wsum; s3[tid] = l1acc; s4[tid] = glacc;
    __syncthreads();
#pragma unroll
    for (int s = 128; s > 0; s >>= 1) {
        if (tid < s) {
            s1[tid] += s1[tid + s];
            s2[tid] += s2[tid + s];
            s3[tid] += s3[tid + s];
            s4[tid] += s4[tid + s];
        }
        __syncthreads();
    }
    if (tid == 0) {
        atomicAdd(&g_cls_num, s1[0]);
        atomicAdd(&g_cls_den, s2[0]);
        atomicAdd(&g_l1, s3[0]);
        atomicAdd(&g_gl, s4[0]);
        __threadfence();
        int done = atomicAdd(&g_loss_done, 1);
        if (done == gridDim.x - 1) {   // last block finalizes
            int nm = g_nmatched;
            if (nm < 1) nm = 1;
            double nmd = (double)nm;
            double cls = g_cls_num / g_cls_den;
            out[0] = (float)(2.0 * cls + 5.0 * g_l1 / nmd + 2.0 * g_gl / nmd);
        }
    }
}

extern "C" void kernel_launch(void* const* d_in, const int* in_sizes, int n_in,
                              void* d_out, int out_size) {
    const float* pred_logits = (const float*)d_in[0];
    const float* pred_boxes  = (const float*)d_in[1];
    const int*   gt_classes  = (const int*)d_in[2];
    const float* gt_boxes    = (const float*)d_in[3];
    float* out = (float*)d_out;

    prep_kernel<<<BB, 32>>>(gt_classes);

    dim3 cgrid((QQ + 127) / 128, BB);
    cost_kernel<<<cgrid, 128>>>(pred_logits, pred_boxes, gt_classes, gt_boxes);

    dim3 rgrid(GG, BB);
    rowmin_kernel<<<rgrid, 256>>>();

    jv_kernel<<<BB, 32>>>();

    int total = BB * QQ;
    loss_kernel<<<(total + 255) / 256, 256>>>(pred_logits, pred_boxes,
                                              gt_classes, gt_boxes, out);
}

// round 10
// speedup vs baseline: 1.2807x; 1.1343x over previous
#include <cuda_runtime.h>
#include <math.h>

#define BB 64
#define QQ 900
#define GG 100
#define NC 10
#define NC1 11
#define NF4 225    // 900/4 float4 per row

// -------- device scratch (static: no allocation) --------
__device__ float  g_costT[BB * GG * QQ];   // transposed cost: [b][k][q]
__device__ float  g_logZ[BB * QQ];         // log-partition per (b,q), reused by loss
__device__ int    g_vlist[BB * GG];
__device__ int    g_nvalid[BB];
__device__ float  g_rowminval[BB * GG];
__device__ int    g_rowminidx[BB * GG];
__device__ int    g_match[BB * QQ];
__device__ int    g_nmatched;
__device__ int    g_loss_done;
__device__ double g_cls_num;
__device__ double g_cls_den;
__device__ double g_l1;
__device__ double g_gl;

// ordered-uint key: monotone map float -> uint32 (handles negatives)
__device__ __forceinline__ unsigned int fkey(float f) {
    unsigned int b = __float_as_uint(f);
    return (b & 0x80000000u) ? ~b : (b | 0x80000000u);
}

// one block per batch: compact valid gt indices (+ global init on block 0)
__global__ void prep_kernel(const int* __restrict__ gt_classes) {
    int b = blockIdx.x;
    if (threadIdx.x == 0) {
        if (b == 0) {
            g_nmatched = 0;
            g_loss_done = 0;
            g_cls_num = 0.0;
            g_cls_den = 0.0;
            g_l1 = 0.0;
            g_gl = 0.0;
        }
        int n = 0;
        for (int g = 0; g < GG; g++) {
            if (gt_classes[b * GG + g] >= 0) g_vlist[b * GG + n++] = g;
        }
        g_nvalid[b] = n;
    }
}

// cost[b][q][k] -> g_costT[(b*GG + k)*QQ + q]; also writes logZ per (b,q)
__global__ void cost_kernel(const float* __restrict__ logits,
                            const float* __restrict__ pboxes,
                            const int*   __restrict__ gtc,
                            const float* __restrict__ gboxes) {
    int b = blockIdx.y;
    int q = blockIdx.x * blockDim.x + threadIdx.x;

    __shared__ float sgx0[GG], sgy0[GG], sgx1[GG], sgy1[GG], sga[GG];
    __shared__ float sgcx[GG], sgcy[GG], sgw[GG], sgh[GG];
    __shared__ int   scls[GG];
    __shared__ int   sn;

    if (threadIdx.x == 0) sn = g_nvalid[b];
    __syncthreads();
    int n = sn;

    for (int k = threadIdx.x; k < n; k += blockDim.x) {
        int gi = g_vlist[b * GG + k];
        const float* gb = gboxes + ((size_t)(b * GG + gi)) * 4;
        float cx = gb[0], cy = gb[1], w = gb[2], h = gb[3];
        float x0 = cx - w * 0.5f, y0 = cy - h * 0.5f;
        float x1 = cx + w * 0.5f, y1 = cy + h * 0.5f;
        sgx0[k] = x0; sgy0[k] = y0; sgx1[k] = x1; sgy1[k] = y1;
        sga[k] = fmaxf(x1 - x0, 0.f) * fmaxf(y1 - y0, 0.f);
        sgcx[k] = cx; sgcy[k] = cy; sgw[k] = w; sgh[k] = h;
        int c = gtc[b * GG + gi];
        scls[k] = (c < 0) ? 0 : (c > NC - 1 ? NC - 1 : c);
    }
    __syncthreads();
    if (q >= QQ) return;

    // softmax over NC1 logits
    const float* lg = logits + ((size_t)(b * QQ + q)) * NC1;
    float e[NC1];
    float mx = lg[0];
#pragma unroll
    for (int c = 1; c < NC1; c++) mx = fmaxf(mx, lg[c]);
    float s = 0.f;
#pragma unroll
    for (int c = 0; c < NC1; c++) { e[c] = expf(lg[c] - mx); s += e[c]; }
    float inv_s = 1.0f / s;
    g_logZ[b * QQ + q] = mx + logf(s);   // reused by loss_kernel

    const float* pb = pboxes + ((size_t)(b * QQ + q)) * 4;
    float pcx = pb[0], pcy = pb[1], pw = pb[2], ph = pb[3];
    float px0 = pcx - pw * 0.5f, py0 = pcy - ph * 0.5f;
    float px1 = pcx + pw * 0.5f, py1 = pcy + ph * 0.5f;
    float pa = fmaxf(px1 - px0, 0.f) * fmaxf(py1 - py0, 0.f);

    float* outc = g_costT + (size_t)b * GG * QQ + q;
    for (int k = 0; k < n; k++) {
        float clsc = -(e[scls[k]] * inv_s);
        float l1 = fabsf(pcx - sgcx[k]) + fabsf(pcy - sgcy[k]) +
                   fabsf(pw - sgw[k]) + fabsf(ph - sgh[k]);
        float gx0 = sgx0[k], gy0 = sgy0[k], gx1 = sgx1[k], gy1 = sgy1[k];
        float ltx = fmaxf(px0, gx0), lty = fmaxf(py0, gy0);
        float rbx = fminf(px1, gx1), rby = fminf(py1, gy1);
        float iw = fmaxf(rbx - ltx, 0.f), ih = fmaxf(rby - lty, 0.f);
        float inter = iw * ih;
        float uni = pa + sga[k] - inter;
        float iou = inter / fmaxf(uni, 1e-6f);
        float ex0 = fminf(px0, gx0), ey0 = fminf(py0, gy0);
        float ex1 = fmaxf(px1, gx1), ey1 = fmaxf(py1, gy1);
        float ew = fmaxf(ex1 - ex0, 0.f), eh = fmaxf(ey1 - ey0, 0.f);
        float enc = ew * eh;
        float giou = iou - (enc - uni) / fmaxf(enc, 1e-6f);
        outc[(size_t)k * QQ] = 2.0f * clsc + 5.0f * l1 - 2.0f * giou;
    }
}

// one block per (row k, batch b): min+argmin over the 900-entry cost row.
__global__ void __launch_bounds__(256) rowmin_kernel() {
    const int k = blockIdx.x;
    const int b = blockIdx.y;
    if (k >= g_nvalid[b]) return;

    const float4* __restrict__ Crow4 =
        (const float4*)(g_costT + ((size_t)(b * GG + k)) * QQ);
    const int tid = threadIdx.x;

    float bestv = 1e30f;
    int bestq = QQ;
    if (tid < NF4) {
        float4 v = __ldg(&Crow4[tid]);
        int q0 = tid * 4;
        bestv = v.x; bestq = q0;
        if (v.y < bestv) { bestv = v.y; bestq = q0 + 1; }
        if (v.z < bestv) { bestv = v.z; bestq = q0 + 2; }
        if (v.w < bestv) { bestv = v.w; bestq = q0 + 3; }
    }
    unsigned long long best =
        ((unsigned long long)fkey(bestv) << 32) | (unsigned int)bestq;
#pragma unroll
    for (int off = 16; off; off >>= 1) {
        unsigned long long o = __shfl_down_sync(0xffffffffu, best, off);
        if (o < best) best = o;
    }
    __shared__ unsigned long long sw[8];
    if ((tid & 31) == 0) sw[tid >> 5] = best;
    __syncthreads();
    if (tid == 0) {
        unsigned long long bb = sw[0];
#pragma unroll
        for (int w = 1; w < 8; w++) if (sw[w] < bb) bb = sw[w];
        int q = (int)(bb & 0xFFFFFFFFull);
        g_rowminval[b * GG + k] = ((const float*)Crow4)[q];
        g_rowminidx[b * GG + k] = q;
    }
}

// Warm-started Jonker-Volgenant, 1 warp per batch, float32 duals (v=0 start —
// the fp32-safe variant verified exact in R4/R5/R8/R9). 0-based columns,
// root column = -1. Lane owns float4 chunks: q in [4*(lane+32s), +3].
__global__ void __launch_bounds__(32) jv_kernel() {
    const int b = blockIdx.x;
    const int lane = threadIdx.x;
    const int n = g_nvalid[b];
    const float FNAN = __int_as_float(0x7fc00000);

    __shared__ __align__(16) float sv[QQ + 4];     // v duals
    __shared__ __align__(16) float sminv[QQ + 4];  // path minima (NaN = used)
    __shared__ float su[GG];                       // u duals
    __shared__ int   sway[QQ + 4];
    __shared__ int   sp[QQ + 4];                   // assigned row per col, -1 free
    __shared__ int   susedList[GG + 2];
    __shared__ float sDused[GG + 2];
    __shared__ int   sfree[GG + 1];
    __shared__ float srowval[GG];
    __shared__ int   srowidx[GG];
    __shared__ int   snfree;

    for (int q = lane; q < QQ + 4; q += 32) { sv[q] = 0.0f; sp[q] = -1; }
    for (int i = lane; i < n; i += 32) {
        srowval[i] = g_rowminval[b * GG + i];
        srowidx[i] = g_rowminidx[b * GG + i];
    }
    __syncwarp();

    // greedy assignment from row minima (decisions serial, data from LDS)
    if (lane == 0) {
        int nf = 0;
        for (int i = 0; i < n; i++) {
            su[i] = srowval[i];
            int jm = srowidx[i];
            if (sp[jm] < 0) sp[jm] = i;
            else sfree[nf++] = i;
        }
        snfree = nf;
    }
    __syncwarp();
    const int nfree = snfree;

    const float* Cbase = g_costT + (size_t)b * GG * QQ;

    for (int fi = 0; fi < nfree; fi++) {
        const int f = sfree[fi];
        // reset minv (vectorized)
#pragma unroll
        for (int s = 0; s < 8; s++) {
            int f4 = lane + (s << 5);
            if (f4 < NF4)
                *(float4*)&sminv[f4 << 2] = make_float4(1e30f, 1e30f, 1e30f, 1e30f);
        }
        __syncwarp();

        int i0 = f;
        int j0 = -1;       // root
        float D = 0.0f;
        int cnt = 0;

        while (true) {
            const float ueff = su[i0] - D;
            if (lane == 0) { susedList[cnt] = j0; sDused[cnt] = D; }
            if (j0 >= 0 && (((j0 >> 2) & 31) == lane)) sminv[j0] = FNAN; // owner marks used
            cnt++;

            const float4* __restrict__ Crow4 =
                (const float4*)(Cbase + (size_t)i0 * QQ);

            // batched vector loads: full MLP, one L2 round trip
            float4 c4[8];
#pragma unroll
            for (int s = 0; s < 8; s++) {
                int f4 = lane + (s << 5);
                c4[s] = (f4 < NF4) ? __ldg(&Crow4[f4])
                                   : make_float4(1e30f, 1e30f, 1e30f, 1e30f);
            }

            float lmin = 1e30f;
            int lq = QQ;
#pragma unroll
            for (int s = 0; s < 8; s++) {
                int f4 = lane + (s << 5);
                if (f4 < NF4) {
                    int q0 = f4 << 2;
                    float4 v4 = *(const float4*)&sv[q0];
                    float4 m4 = *(const float4*)&sminv[q0];
                    float cur;
                    cur = c4[s].x - ueff - v4.x;
                    if (cur < m4.x) { m4.x = cur; sway[q0] = j0; }       // false if NaN
                    cur = c4[s].y - ueff - v4.y;
                    if (cur < m4.y) { m4.y = cur; sway[q0 + 1] = j0; }
                    cur = c4[s].z - ueff - v4.z;
                    if (cur < m4.z) { m4.z = cur; sway[q0 + 2] = j0; }
                    cur = c4[s].w - ueff - v4.w;
                    if (cur < m4.w) { m4.w = cur; sway[q0 + 3] = j0; }
                    *(float4*)&sminv[q0] = m4;
                    if (m4.x < lmin) { lmin = m4.x; lq = q0; }           // NaN excluded
                    if (m4.y < lmin) { lmin = m4.y; lq = q0 + 1; }
                    if (m4.z < lmin) { lmin = m4.z; lq = q0 + 2; }
                    if (m4.w < lmin) { lmin = m4.w; lq = q0 + 3; }
                }
            }
            // warp (value, index) min-reduce; tie -> smaller q (== np.argmin)
#pragma unroll
            for (int off = 16; off; off >>= 1) {
                float ov = __shfl_down_sync(0xffffffffu, lmin, off);
                int   oi = __shfl_down_sync(0xffffffffu, lq, off);
                if (ov < lmin || (ov == lmin && oi < lq)) { lmin = ov; lq = oi; }
            }
            D  = __shfl_sync(0xffffffffu, lmin, 0);  // new cumulative offset
            j0 = __shfl_sync(0xffffffffu, lq, 0);
            int pj = sp[j0];
            if (pj < 0) break;
            i0 = pj;
        }

        // commit duals over used columns (distinct rows & cols -> race-free)
        __syncwarp();
        for (int t = lane; t < cnt; t += 32) {
            int j = susedList[t];
            float dd = D - sDused[t];
            if (j < 0) su[f] += dd;
            else { su[sp[j]] += dd; sv[j] -= dd; }
        }
        __syncwarp();
        if (lane == 0) {
            int jj = j0;
            while (jj >= 0) {
                int jn = sway[jj];
                sp[jj] = (jn < 0) ? f : sp[jn];
                jj = jn;
            }
        }
        __syncwarp();
    }

    for (int q = lane; q < QQ; q += 32) {
        int r = sp[q];
        g_match[b * QQ + q] = (r >= 0) ? g_vlist[b * GG + r] : -1;
    }
    if (lane == 0) atomicAdd(&g_nmatched, n);
}

__global__ void loss_kernel(const float* __restrict__ logits,
                            const float* __restrict__ pboxes,
                            const int*   __restrict__ gtc,
                            const float* __restrict__ gboxes,
                            float* __restrict__ out) {
    int idx = blockIdx.x * blockDim.x + threadIdx.x;
    double nllw = 0.0, wsum = 0.0, l1acc = 0.0, glacc = 0.0;

    if (idx < BB * QQ) {
        int b = idx / QQ;
        int mg = g_match[idx];
        int t = (mg >= 0) ? gtc[b * GG + mg] : NC;
        float logp = logits[(size_t)idx * NC1 + t] - g_logZ[idx];
        float wt = (t == NC) ? 0.1f : 1.0f;
        nllw = (double)(wt * (-logp));
        wsum = (double)wt;

        if (mg >= 0) {
            const float* pb = pboxes + (size_t)idx * 4;
            const float* gb = gboxes + ((size_t)(b * GG + mg)) * 4;
            float pcx = pb[0], pcy = pb[1], pw = pb[2], ph = pb[3];
            float gcx = gb[0], gcy = gb[1], gw = gb[2], gh = gb[3];
            l1acc = (double)(fabsf(pcx - gcx) + fabsf(pcy - gcy) +
                             fabsf(pw - gw) + fabsf(ph - gh));
            float px0 = pcx - pw * 0.5f, py0 = pcy - ph * 0.5f;
            float px1 = pcx + pw * 0.5f, py1 = pcy + ph * 0.5f;
            float gx0 = gcx - gw * 0.5f, gy0 = gcy - gh * 0.5f;
            float gx1 = gcx + gw * 0.5f, gy1 = gcy + gh * 0.5f;
            float pa = fmaxf(px1 - px0, 0.f) * fmaxf(py1 - py0, 0.f);
            float ga = fmaxf(gx1 - gx0, 0.f) * fmaxf(gy1 - gy0, 0.f);
            float ltx = fmaxf(px0, gx0), lty = fmaxf(py0, gy0);
            float rbx = fminf(px1, gx1), rby = fminf(py1, gy1);
            float iw = fmaxf(rbx - ltx, 0.f), ih = fmaxf(rby - lty, 0.f);
            float inter = iw * ih;
            float uni = pa + ga - inter;
            float iou = inter / fmaxf(uni, 1e-6f);
            float ex0 = fminf(px0, gx0), ey0 = fminf(py0, gy0);
            float ex1 = fmaxf(px1, gx1), ey1 = fmaxf(py1, gy1);
            float ew = fmaxf(ex1 - ex0, 0.f), eh = fmaxf(ey1 - ey0, 0.f);
            float enc = ew * eh;
            float giou = iou - (enc - uni) / fmaxf(enc, 1e-6f);
            glacc = (double)(1.0f - giou);
        }
    }

    __shared__ double s1[256], s2[256], s3[256], s4[256];
    int tid = threadIdx.x;
    s1[tid] = nllw; s2[tid] = wsum; s3[tid] = l1acc; s4[tid] = glacc;
    __syncthreads();
#pragma unroll
    for (int s = 128; s > 0; s >>= 1) {
        if (tid < s) {
            s1[tid] += s1[tid + s];
            s2[tid] += s2[tid + s];
            s3[tid] += s3[tid + s];
            s4[tid] += s4[tid + s];
        }
        __syncthreads();
    }
    if (tid == 0) {
        atomicAdd(&g_cls_num, s1[0]);
        atomicAdd(&g_cls_den, s2[0]);
        atomicAdd(&g_l1, s3[0]);
        atomicAdd(&g_gl, s4[0]);
        __threadfence();
        int done = atomicAdd(&g_loss_done, 1);
        if (done == gridDim.x - 1) {   // last block finalizes
            int nm = g_nmatched;
            if (nm < 1) nm = 1;
            double nmd = (double)nm;
            double cls = g_cls_num / g_cls_den;
            out[0] = (float)(2.0 * cls + 5.0 * g_l1 / nmd + 2.0 * g_gl / nmd);
        }
    }
}

extern "C" void kernel_launch(void* const* d_in, const int* in_sizes, int n_in,
                              void* d_out, int out_size) {
    const float* pred_logits = (const float*)d_in[0];
    const float* pred_boxes  = (const float*)d_in[1];
    const int*   gt_classes  = (const int*)d_in[2];
    const float* gt_boxes    = (const float*)d_in[3];
    float* out = (float*)d_out;

    prep_kernel<<<BB, 32>>>(gt_classes);

    dim3 cgrid((QQ + 127) / 128, BB);
    cost_kernel<<<cgrid, 128>>>(pred_logits, pred_boxes, gt_classes, gt_boxes);

    dim3 rgrid(GG, BB);
    rowmin_kernel<<<rgrid, 256>>>();

    jv_kernel<<<BB, 32>>>();

    int total = BB * QQ;
    loss_kernel<<<(total + 255) / 256, 256>>>(pred_logits, pred_boxes,
                                              gt_classes, gt_boxes, out);
}

// round 11
// speedup vs baseline: 1.5927x; 1.2436x over previous
#include <cuda_runtime.h>
#include <math.h>

#define BB 64
#define QQ 900
#define GG 100
#define NC 10
#define NC1 11
#define NF4 225    // 900/4 float4 per row
#define KCHUNK 25  // gt rows per cost-kernel z-block

// -------- device scratch (static: no allocation) --------
__device__ float  g_costT[BB * GG * QQ];   // transposed cost: [b][k][q]
__device__ float  g_logZ[BB * QQ];         // log-partition per (b,q), reused by loss
__device__ int    g_vlist[BB * GG];
__device__ int    g_nvalid[BB];
__device__ float  g_rowminval[BB * GG];
__device__ int    g_rowminidx[BB * GG];
__device__ int    g_match[BB * QQ];
__device__ int    g_nmatched;
__device__ int    g_loss_done;
__device__ double g_cls_num;
__device__ double g_cls_den;
__device__ double g_l1;
__device__ double g_gl;

// ordered-uint key: monotone bijection float -> uint32 (handles negatives)
__device__ __forceinline__ unsigned int fkey(float f) {
    unsigned int b = __float_as_uint(f);
    return (b & 0x80000000u) ? ~b : (b | 0x80000000u);
}
__device__ __forceinline__ float fkey_inv(unsigned int key) {
    unsigned int b = (key & 0x80000000u) ? (key ^ 0x80000000u) : ~key;
    return __uint_as_float(b);
}

// one block per batch: compact valid gt indices (+ global init on block 0)
__global__ void prep_kernel(const int* __restrict__ gt_classes) {
    int b = blockIdx.x;
    if (threadIdx.x == 0) {
        if (b == 0) {
            g_nmatched = 0;
            g_loss_done = 0;
            g_cls_num = 0.0;
            g_cls_den = 0.0;
            g_l1 = 0.0;
            g_gl = 0.0;
        }
        int n = 0;
        for (int g = 0; g < GG; g++) {
            if (gt_classes[b * GG + g] >= 0) g_vlist[b * GG + n++] = g;
        }
        g_nvalid[b] = n;
    }
}

// cost[b][q][k] -> g_costT[(b*GG + k)*QQ + q]; k split across gridDim.z
// chunks of KCHUNK; logZ written by z==0 only.
__global__ void cost_kernel(const float* __restrict__ logits,
                            const float* __restrict__ pboxes,
                            const int*   __restrict__ gtc,
                            const float* __restrict__ gboxes) {
    int b = blockIdx.y;
    int q = blockIdx.x * blockDim.x + threadIdx.x;
    int kc0 = blockIdx.z * KCHUNK;

    __shared__ float sgx0[KCHUNK], sgy0[KCHUNK], sgx1[KCHUNK], sgy1[KCHUNK], sga[KCHUNK];
    __shared__ float sgcx[KCHUNK], sgcy[KCHUNK], sgw[KCHUNK], sgh[KCHUNK];
    __shared__ int   scls[KCHUNK];
    __shared__ int   sn;

    if (threadIdx.x == 0) sn = g_nvalid[b];
    __syncthreads();
    int n = sn;
    int kc1 = min(n, kc0 + KCHUNK);
    if (kc0 >= kc1 && blockIdx.z != 0) return;   // block-uniform

    for (int k = kc0 + threadIdx.x; k < kc1; k += blockDim.x) {
        int kk = k - kc0;
        int gi = g_vlist[b * GG + k];
        const float* gb = gboxes + ((size_t)(b * GG + gi)) * 4;
        float cx = gb[0], cy = gb[1], w = gb[2], h = gb[3];
        float x0 = cx - w * 0.5f, y0 = cy - h * 0.5f;
        float x1 = cx + w * 0.5f, y1 = cy + h * 0.5f;
        sgx0[kk] = x0; sgy0[kk] = y0; sgx1[kk] = x1; sgy1[kk] = y1;
        sga[kk] = fmaxf(x1 - x0, 0.f) * fmaxf(y1 - y0, 0.f);
        sgcx[kk] = cx; sgcy[kk] = cy; sgw[kk] = w; sgh[kk] = h;
        int c = gtc[b * GG + gi];
        scls[kk] = (c < 0) ? 0 : (c > NC - 1 ? NC - 1 : c);
    }
    __syncthreads();
    if (q >= QQ) return;

    // softmax over NC1 logits
    const float* lg = logits + ((size_t)(b * QQ + q)) * NC1;
    float e[NC1];
    float mx = lg[0];
#pragma unroll
    for (int c = 1; c < NC1; c++) mx = fmaxf(mx, lg[c]);
    float s = 0.f;
#pragma unroll
    for (int c = 0; c < NC1; c++) { e[c] = expf(lg[c] - mx); s += e[c]; }
    float inv_s = 1.0f / s;
    if (blockIdx.z == 0) g_logZ[b * QQ + q] = mx + logf(s);

    const float* pb = pboxes + ((size_t)(b * QQ + q)) * 4;
    float pcx = pb[0], pcy = pb[1], pw = pb[2], ph = pb[3];
    float px0 = pcx - pw * 0.5f, py0 = pcy - ph * 0.5f;
    float px1 = pcx + pw * 0.5f, py1 = pcy + ph * 0.5f;
    float pa = fmaxf(px1 - px0, 0.f) * fmaxf(py1 - py0, 0.f);

    float* outc = g_costT + (size_t)b * GG * QQ + q;
    for (int k = kc0; k < kc1; k++) {
        int kk = k - kc0;
        float clsc = -(e[scls[kk]] * inv_s);
        float l1 = fabsf(pcx - sgcx[kk]) + fabsf(pcy - sgcy[kk]) +
                   fabsf(pw - sgw[kk]) + fabsf(ph - sgh[kk]);
        float gx0 = sgx0[kk], gy0 = sgy0[kk], gx1 = sgx1[kk], gy1 = sgy1[kk];
        float ltx = fmaxf(px0, gx0), lty = fmaxf(py0, gy0);
        float rbx = fminf(px1, gx1), rby = fminf(py1, gy1);
        float iw = fmaxf(rbx - ltx, 0.f), ih = fmaxf(rby - lty, 0.f);
        float inter = iw * ih;
        float uni = pa + sga[kk] - inter;
        float iou = inter / fmaxf(uni, 1e-6f);
        float ex0 = fminf(px0, gx0), ey0 = fminf(py0, gy0);
        float ex1 = fmaxf(px1, gx1), ey1 = fmaxf(py1, gy1);
        float ew = fmaxf(ex1 - ex0, 0.f), eh = fmaxf(ey1 - ey0, 0.f);
        float enc = ew * eh;
        float giou = iou - (enc - uni) / fmaxf(enc, 1e-6f);
        outc[(size_t)k * QQ] = 2.0f * clsc + 5.0f * l1 - 2.0f * giou;
    }
}

// one block per (row k, batch b): min+argmin over the 900-entry cost row.
__global__ void __launch_bounds__(256) rowmin_kernel() {
    const int k = blockIdx.x;
    const int b = blockIdx.y;
    if (k >= g_nvalid[b]) return;

    const float4* __restrict__ Crow4 =
        (const float4*)(g_costT + ((size_t)(b * GG + k)) * QQ);
    const int tid = threadIdx.x;

    float bestv = 1e30f;
    int bestq = QQ;
    if (tid < NF4) {
        float4 v = __ldg(&Crow4[tid]);
        int q0 = tid * 4;
        bestv = v.x; bestq = q0;
        if (v.y < bestv) { bestv = v.y; bestq = q0 + 1; }
        if (v.z < bestv) { bestv = v.z; bestq = q0 + 2; }
        if (v.w < bestv) { bestv = v.w; bestq = q0 + 3; }
    }
    unsigned long long best =
        ((unsigned long long)fkey(bestv) << 32) | (unsigned int)bestq;
#pragma unroll
    for (int off = 16; off; off >>= 1) {
        unsigned long long o = __shfl_down_sync(0xffffffffu, best, off);
        if (o < best) best = o;
    }
    __shared__ unsigned long long sw[8];
    if ((tid & 31) == 0) sw[tid >> 5] = best;
    __syncthreads();
    if (tid == 0) {
        unsigned long long bb = sw[0];
#pragma unroll
        for (int w = 1; w < 8; w++) if (sw[w] < bb) bb = sw[w];
        int q = (int)(bb & 0xFFFFFFFFull);
        g_rowminval[b * GG + k] = ((const float*)Crow4)[q];
        g_rowminidx[b * GG + k] = q;
    }
}

// Warm-started Jonker-Volgenant, 1 warp per batch, float32 duals (v=0 start —
// the fp32-safe variant verified exact in R4/R5/R8/R9/R10). 0-based columns,
// root column = -1. Lane owns float4 chunks. Warp argmin via redux.sync:
// min over exact fkey, then min q among exact ties (== np.argmin semantics).
__global__ void __launch_bounds__(32) jv_kernel() {
    const int b = blockIdx.x;
    const int lane = threadIdx.x;
    const int n = g_nvalid[b];
    const float FNAN = __int_as_float(0x7fc00000);

    __shared__ __align__(16) float sv[QQ + 4];     // v duals
    __shared__ __align__(16) float sminv[QQ + 4];  // path minima (NaN = used)
    __shared__ float su[GG];                       // u duals
    __shared__ int   sway[QQ + 4];
    __shared__ int   sp[QQ + 4];                   // assigned row per col, -1 free
    __shared__ int   susedList[GG + 2];
    __shared__ float sDused[GG + 2];
    __shared__ int   sfree[GG + 1];
    __shared__ float srowval[GG];
    __shared__ int   srowidx[GG];
    __shared__ int   snfree;

    for (int q = lane; q < QQ + 4; q += 32) { sv[q] = 0.0f; sp[q] = -1; }
    for (int i = lane; i < n; i += 32) {
        srowval[i] = g_rowminval[b * GG + i];
        srowidx[i] = g_rowminidx[b * GG + i];
    }
    __syncwarp();

    // greedy assignment from row minima (decisions serial, data from LDS)
    if (lane == 0) {
        int nf = 0;
        for (int i = 0; i < n; i++) {
            su[i] = srowval[i];
            int jm = srowidx[i];
            if (sp[jm] < 0) sp[jm] = i;
            else sfree[nf++] = i;
        }
        snfree = nf;
    }
    __syncwarp();
    const int nfree = snfree;

    const float* Cbase = g_costT + (size_t)b * GG * QQ;

    for (int fi = 0; fi < nfree; fi++) {
        const int f = sfree[fi];
        // reset minv (vectorized)
#pragma unroll
        for (int s = 0; s < 8; s++) {
            int f4 = lane + (s << 5);
            if (f4 < NF4)
                *(float4*)&sminv[f4 << 2] = make_float4(1e30f, 1e30f, 1e30f, 1e30f);
        }
        __syncwarp();

        int i0 = f;
        int j0 = -1;       // root
        float D = 0.0f;
        int cnt = 0;

        while (true) {
            const float ueff = su[i0] - D;
            if (lane == 0) { susedList[cnt] = j0; sDused[cnt] = D; }
            if (j0 >= 0 && (((j0 >> 2) & 31) == lane)) sminv[j0] = FNAN; // owner marks used
            cnt++;

            const float4* __restrict__ Crow4 =
                (const float4*)(Cbase + (size_t)i0 * QQ);

            // batched vector loads: full MLP, one L2 round trip
            float4 c4[8];
#pragma unroll
            for (int s = 0; s < 8; s++) {
                int f4 = lane + (s << 5);
                c4[s] = (f4 < NF4) ? __ldg(&Crow4[f4])
                                   : make_float4(1e30f, 1e30f, 1e30f, 1e30f);
            }

            float lmin = 1e30f;
            int lq = QQ;
#pragma unroll
            for (int s = 0; s < 8; s++) {
                int f4 = lane + (s << 5);
                if (f4 < NF4) {
                    int q0 = f4 << 2;
                    float4 v4 = *(const float4*)&sv[q0];
                    float4 m4 = *(const float4*)&sminv[q0];
                    float cur;
                    cur = c4[s].x - ueff - v4.x;
                    if (cur < m4.x) { m4.x = cur; sway[q0] = j0; }       // false if NaN
                    cur = c4[s].y - ueff - v4.y;
                    if (cur < m4.y) { m4.y = cur; sway[q0 + 1] = j0; }
                    cur = c4[s].z - ueff - v4.z;
                    if (cur < m4.z) { m4.z = cur; sway[q0 + 2] = j0; }
                    cur = c4[s].w - ueff - v4.w;
                    if (cur < m4.w) { m4.w = cur; sway[q0 + 3] = j0; }
                    *(float4*)&sminv[q0] = m4;
                    if (m4.x < lmin) { lmin = m4.x; lq = q0; }           // NaN excluded
                    if (m4.y < lmin) { lmin = m4.y; lq = q0 + 1; }
                    if (m4.z < lmin) { lmin = m4.z; lq = q0 + 2; }
                    if (m4.w < lmin) { lmin = m4.w; lq = q0 + 3; }
                }
            }
            // warp argmin via two hardware reduces (results warp-uniform):
            //  1) min of exact ordered keys  2) min q among exact-key ties
            unsigned int key = fkey(lmin);
            unsigned int mkey = __reduce_min_sync(0xffffffffu, key);
            unsigned int qc = (key == mkey) ? (unsigned int)lq : 0xffffffffu;
            unsigned int qmin = __reduce_min_sync(0xffffffffu, qc);
            D = fkey_inv(mkey);          // bit-identical to winning lmin
            j0 = (int)qmin;
            int pj = sp[j0];
            if (pj < 0) break;
            i0 = pj;
        }

        // commit duals over used columns (distinct rows & cols -> race-free)
        __syncwarp();
        for (int t = lane; t < cnt; t += 32) {
            int j = susedList[t];
            float dd = D - sDused[t];
            if (j < 0) su[f] += dd;
            else { su[sp[j]] += dd; sv[j] -= dd; }
        }
        __syncwarp();
        if (lane == 0) {
            int jj = j0;
            while (jj >= 0) {
                int jn = sway[jj];
                sp[jj] = (jn < 0) ? f : sp[jn];
                jj = jn;
            }
        }
        __syncwarp();
    }

    for (int q = lane; q < QQ; q += 32) {
        int r = sp[q];
        g_match[b * QQ + q] = (r >= 0) ? g_vlist[b * GG + r] : -1;
    }
    if (lane == 0) atomicAdd(&g_nmatched, n);
}

__global__ void loss_kernel(const float* __restrict__ logits,
                            const float* __restrict__ pboxes,
                            const int*   __restrict__ gtc,
                            const float* __restrict__ gboxes,
                            float* __restrict__ out) {
    int idx = blockIdx.x * blockDim.x + threadIdx.x;
    double nllw = 0.0, wsum = 0.0, l1acc = 0.0, glacc = 0.0;

    if (idx < BB * QQ) {
        int b = idx / QQ;
        int mg = g_match[idx];
        int t = (mg >= 0) ? gtc[b * GG + mg] : NC;
        float logp = logits[(size_t)idx * NC1 + t] - g_logZ[idx];
        float wt = (t == NC) ? 0.1f : 1.0f;
        nllw = (double)(wt * (-logp));
        wsum = (double)wt;

        if (mg >= 0) {
            const float* pb = pboxes + (size_t)idx * 4;
            const float* gb = gboxes + ((size_t)(b * GG + mg)) * 4;
            float pcx = pb[0], pcy = pb[1], pw = pb[2], ph = pb[3];
            float gcx = gb[0], gcy = gb[1], gw = gb[2], gh = gb[3];
            l1acc = (double)(fabsf(pcx - gcx) + fabsf(pcy - gcy) +
                             fabsf(pw - gw) + fabsf(ph - gh));
            float px0 = pcx - pw * 0.5f, py0 = pcy - ph * 0.5f;
            float px1 = pcx + pw * 0.5f, py1 = pcy + ph * 0.5f;
            float gx0 = gcx - gw * 0.5f, gy0 = gcy - gh * 0.5f;
            float gx1 = gcx + gw * 0.5f, gy1 = gcy + gh * 0.5f;
            float pa = fmaxf(px1 - px0, 0.f) * fmaxf(py1 - py0, 0.f);
            float ga = fmaxf(gx1 - gx0, 0.f) * fmaxf(gy1 - gy0, 0.f);
            float ltx = fmaxf(px0, gx0), lty = fmaxf(py0, gy0);
            float rbx = fminf(px1, gx1), rby = fminf(py1, gy1);
            float iw = fmaxf(rbx - ltx, 0.f), ih = fmaxf(rby - lty, 0.f);
            float inter = iw * ih;
            float uni = pa + ga - inter;
            float iou = inter / fmaxf(uni, 1e-6f);
            float ex0 = fminf(px0, gx0), ey0 = fminf(py0, gy0);
            float ex1 = fmaxf(px1, gx1), ey1 = fmaxf(py1, gy1);
            float ew = fmaxf(ex1 - ex0, 0.f), eh = fmaxf(ey1 - ey0, 0.f);
            float enc = ew * eh;
            float giou = iou - (enc - uni) / fmaxf(enc, 1e-6f);
            glacc = (double)(1.0f - giou);
        }
    }

    __shared__ double s1[256], s2[256], s3[256], s4[256];
    int tid = threadIdx.x;
    s1[tid] = nllw; s2[tid] = wsum; s3[tid] = l1acc; s4[tid] = glacc;
    __syncthreads();
#pragma unroll
    for (int s = 128; s > 0; s >>= 1) {
        if (tid < s) {
            s1[tid] += s1[tid + s];
            s2[tid] += s2[tid + s];
            s3[tid] += s3[tid + s];
            s4[tid] += s4[tid + s];
        }
        __syncthreads();
    }
    if (tid == 0) {
        atomicAdd(&g_cls_num, s1[0]);
        atomicAdd(&g_cls_den, s2[0]);
        atomicAdd(&g_l1, s3[0]);
        atomicAdd(&g_gl, s4[0]);
        __threadfence();
        int done = atomicAdd(&g_loss_done, 1);
        if (done == gridDim.x - 1) {   // last block finalizes
            int nm = g_nmatched;
            if (nm < 1) nm = 1;
            double nmd = (double)nm;
            double cls = g_cls_num / g_cls_den;
            out[0] = (float)(2.0 * cls + 5.0 * g_l1 / nmd + 2.0 * g_gl / nmd);
        }
    }
}

extern "C" void kernel_launch(void* const* d_in, const int* in_sizes, int n_in,
                              void* d_out, int out_size) {
    const float* pred_logits = (const float*)d_in[0];
    const float* pred_boxes  = (const float*)d_in[1];
    const int*   gt_classes  = (const int*)d_in[2];
    const float* gt_boxes    = (const float*)d_in[3];
    float* out = (float*)d_out;

    prep_kernel<<<BB, 32>>>(gt_classes);

    dim3 cgrid((QQ + 127) / 128, BB, (GG + KCHUNK - 1) / KCHUNK);
    cost_kernel<<<cgrid, 128>>>(pred_logits, pred_boxes, gt_classes, gt_boxes);

    dim3 rgrid(GG, BB);
    rowmin_kernel<<<rgrid, 256>>>();

    jv_kernel<<<BB, 32>>>();

    int total = BB * QQ;
    loss_kernel<<<(total + 255) / 256, 256>>>(pred_logits, pred_boxes,
                                              gt_classes, gt_boxes, out);
}

// round 12
// speedup vs baseline: 1.6945x; 1.0639x over previous
#include <cuda_runtime.h>
#include <math.h>

#define BB 64
#define QQ 900
#define GG 100
#define NC 10
#define NC1 11
#define NF4 225    // 900/4 float4 per row
#define KCHUNK 25  // gt rows per cost-kernel z-block

// -------- device scratch (static: no allocation) --------
__device__ float  g_costT[BB * GG * QQ];   // transposed cost: [b][k][q]
__device__ float  g_logZ[BB * QQ];         // log-partition per (b,q), reused by loss
__device__ unsigned long long g_rowpack[BB * GG];  // packed (fkey(min), argmin q)
__device__ int    g_vlist[BB * GG];
__device__ int    g_nvalid[BB];
__device__ int    g_match[BB * QQ];
__device__ int    g_nmatched;
__device__ int    g_loss_done;
__device__ double g_cls_num;
__device__ double g_cls_den;
__device__ double g_l1;
__device__ double g_gl;

// ordered-uint key: monotone bijection float -> uint32 (handles negatives)
__device__ __forceinline__ unsigned int fkey(float f) {
    unsigned int b = __float_as_uint(f);
    return (b & 0x80000000u) ? ~b : (b | 0x80000000u);
}
__device__ __forceinline__ float fkey_inv(unsigned int key) {
    unsigned int b = (key & 0x80000000u) ? (key ^ 0x80000000u) : ~key;
    return __uint_as_float(b);
}

// one block per batch: compact valid gt indices, init rowpack (+ globals)
__global__ void prep_kernel(const int* __restrict__ gt_classes) {
    int b = blockIdx.x;
    for (int k = threadIdx.x; k < GG; k += blockDim.x)
        g_rowpack[b * GG + k] = 0xFFFFFFFFFFFFFFFFull;
    if (threadIdx.x == 0) {
        if (b == 0) {
            g_nmatched = 0;
            g_loss_done = 0;
            g_cls_num = 0.0;
            g_cls_den = 0.0;
            g_l1 = 0.0;
            g_gl = 0.0;
        }
        int n = 0;
        for (int g = 0; g < GG; g++) {
            if (gt_classes[b * GG + g] >= 0) g_vlist[b * GG + n++] = g;
        }
        g_nvalid[b] = n;
    }
}

// cost[b][q][k] -> g_costT[(b*GG + k)*QQ + q]; k split across gridDim.z
// chunks of KCHUNK; logZ written by z==0 only. Per-row (min, argmin) fused
// via redux + packed atomicMin (bit-identical: min value, tie -> smallest q).
__global__ void cost_kernel(const float* __restrict__ logits,
                            const float* __restrict__ pboxes,
                            const int*   __restrict__ gtc,
                            const float* __restrict__ gboxes) {
    int b = blockIdx.y;
    int q = blockIdx.x * blockDim.x + threadIdx.x;
    int kc0 = blockIdx.z * KCHUNK;
    const bool valid = q < QQ;
    const int qc = valid ? q : QQ - 1;
    const int lane = threadIdx.x & 31;

    __shared__ float sgx0[KCHUNK], sgy0[KCHUNK], sgx1[KCHUNK], sgy1[KCHUNK], sga[KCHUNK];
    __shared__ float sgcx[KCHUNK], sgcy[KCHUNK], sgw[KCHUNK], sgh[KCHUNK];
    __shared__ int   scls[KCHUNK];
    __shared__ int   sn;

    if (threadIdx.x == 0) sn = g_nvalid[b];
    __syncthreads();
    int n = sn;
    int kc1 = min(n, kc0 + KCHUNK);
    if (kc0 >= kc1) return;   // block-uniform

    for (int k = kc0 + threadIdx.x; k < kc1; k += blockDim.x) {
        int kk = k - kc0;
        int gi = g_vlist[b * GG + k];
        const float* gb = gboxes + ((size_t)(b * GG + gi)) * 4;
        float cx = gb[0], cy = gb[1], w = gb[2], h = gb[3];
        float x0 = cx - w * 0.5f, y0 = cy - h * 0.5f;
        float x1 = cx + w * 0.5f, y1 = cy + h * 0.5f;
        sgx0[kk] = x0; sgy0[kk] = y0; sgx1[kk] = x1; sgy1[kk] = y1;
        sga[kk] = fmaxf(x1 - x0, 0.f) * fmaxf(y1 - y0, 0.f);
        sgcx[kk] = cx; sgcy[kk] = cy; sgw[kk] = w; sgh[kk] = h;
        int c = gtc[b * GG + gi];
        scls[kk] = (c < 0) ? 0 : (c > NC - 1 ? NC - 1 : c);
    }
    __syncthreads();

    // softmax over NC1 logits
    const float* lg = logits + ((size_t)(b * QQ + qc)) * NC1;
    float e[NC1];
    float mx = lg[0];
#pragma unroll
    for (int c = 1; c < NC1; c++) mx = fmaxf(mx, lg[c]);
    float s = 0.f;
#pragma unroll
    for (int c = 0; c < NC1; c++) { e[c] = expf(lg[c] - mx); s += e[c]; }
    float inv_s = 1.0f / s;
    if (blockIdx.z == 0 && valid) g_logZ[b * QQ + q] = mx + logf(s);

    const float* pb = pboxes + ((size_t)(b * QQ + qc)) * 4;
    float pcx = pb[0], pcy = pb[1], pw = pb[2], ph = pb[3];
    float px0 = pcx - pw * 0.5f, py0 = pcy - ph * 0.5f;
    float px1 = pcx + pw * 0.5f, py1 = pcy + ph * 0.5f;
    float pa = fmaxf(px1 - px0, 0.f) * fmaxf(py1 - py0, 0.f);

    float* outc = g_costT + (size_t)b * GG * QQ + q;
    for (int k = kc0; k < kc1; k++) {
        int kk = k - kc0;
        float clsc = -(e[scls[kk]] * inv_s);
        float l1 = fabsf(pcx - sgcx[kk]) + fabsf(pcy - sgcy[kk]) +
                   fabsf(pw - sgw[kk]) + fabsf(ph - sgh[kk]);
        float gx0 = sgx0[kk], gy0 = sgy0[kk], gx1 = sgx1[kk], gy1 = sgy1[kk];
        float ltx = fmaxf(px0, gx0), lty = fmaxf(py0, gy0);
        float rbx = fminf(px1, gx1), rby = fminf(py1, gy1);
        float iw = fmaxf(rbx - ltx, 0.f), ih = fmaxf(rby - lty, 0.f);
        float inter = iw * ih;
        float uni = pa + sga[kk] - inter;
        float iou = inter / fmaxf(uni, 1e-6f);
        float ex0 = fminf(px0, gx0), ey0 = fminf(py0, gy0);
        float ex1 = fmaxf(px1, gx1), ey1 = fmaxf(py1, gy1);
        float ew = fmaxf(ex1 - ex0, 0.f), eh = fmaxf(ey1 - ey0, 0.f);
        float enc = ew * eh;
        float giou = iou - (enc - uni) / fmaxf(enc, 1e-6f);
        float cval = 2.0f * clsc + 5.0f * l1 - 2.0f * giou;
        if (valid) outc[(size_t)k * QQ] = cval;

        // fused row (min, argmin): 2 hardware reduces + 1 packed atomic/warp
        unsigned int key = valid ? fkey(cval) : 0xFFFFFFFFu;
        unsigned int mkey = __reduce_min_sync(0xffffffffu, key);
        unsigned int qsel = (key == mkey) ? (unsigned int)q : 0xFFFFFFFFu;
        unsigned int qmin = __reduce_min_sync(0xffffffffu, qsel);
        if (lane == 0 && mkey != 0xFFFFFFFFu)
            atomicMin(&g_rowpack[b * GG + k],
                      ((unsigned long long)mkey << 32) | qmin);
    }
}

// Warm-started Jonker-Volgenant, 2 warps per batch, float32 duals (v=0 start —
// the fp32-safe variant verified exact R4/R5/R8-R11). 0-based columns, root
// column = -1. Thread owns float4 chunks f4 == tid (mod 64). Cross-warp argmin:
// per-warp redux then packed-key min in smem (tie -> smallest q globally).
__global__ void __launch_bounds__(64) jv_kernel() {
    const int b = blockIdx.x;
    const int tid = threadIdx.x;
    const int wid = tid >> 5;
    const int lane = tid & 31;
    const int n = g_nvalid[b];
    const float FNAN = __int_as_float(0x7fc00000);

    __shared__ __align__(16) float sv[QQ + 4];     // v duals
    __shared__ __align__(16) float sminv[QQ + 4];  // path minima (NaN = used)
    __shared__ float su[GG];                       // u duals
    __shared__ int   sway[QQ + 4];
    __shared__ int   sp[QQ + 4];                   // assigned row per col, -1 free
    __shared__ int   susedList[GG + 2];
    __shared__ float sDused[GG + 2];
    __shared__ int   sfree[GG + 1];
    __shared__ unsigned long long srowpk[GG];
    __shared__ unsigned long long swcomb[2];
    __shared__ int   snfree;

    for (int q = tid; q < QQ + 4; q += 64) { sv[q] = 0.0f; sp[q] = -1; }
    for (int i = tid; i < n; i += 64) srowpk[i] = g_rowpack[b * GG + i];
    __syncthreads();

    // greedy assignment from row minima (decisions serial, data from LDS)
    if (tid == 0) {
        int nf = 0;
        for (int i = 0; i < n; i++) {
            unsigned long long pk = srowpk[i];
            su[i] = fkey_inv((unsigned int)(pk >> 32));
            int jm = (int)(pk & 0xFFFFFFFFull);
            if (sp[jm] < 0) sp[jm] = i;
            else sfree[nf++] = i;
        }
        snfree = nf;
    }
    __syncthreads();
    const int nfree = snfree;

    const float* Cbase = g_costT + (size_t)b * GG * QQ;

    for (int fi = 0; fi < nfree; fi++) {
        const int f = sfree[fi];
        // reset minv (vectorized, owner-exclusive)
#pragma unroll
        for (int s = 0; s < 4; s++) {
            int f4 = tid + (s << 6);
            if (f4 < NF4)
                *(float4*)&sminv[f4 << 2] = make_float4(1e30f, 1e30f, 1e30f, 1e30f);
        }
        __syncthreads();

        int i0 = f;
        int j0 = -1;       // root
        float D = 0.0f;
        int cnt = 0;

        while (true) {
            const float ueff = su[i0] - D;
            if (tid == 0) { susedList[cnt] = j0; sDused[cnt] = D; }
            if (j0 >= 0 && (((j0 >> 2) & 63) == tid)) sminv[j0] = FNAN; // owner marks used
            cnt++;

            const float4* __restrict__ Crow4 =
                (const float4*)(Cbase + (size_t)i0 * QQ);

            // batched vector loads: full MLP, one L2 round trip
            float4 c4[4];
#pragma unroll
            for (int s = 0; s < 4; s++) {
                int f4 = tid + (s << 6);
                c4[s] = (f4 < NF4) ? __ldg(&Crow4[f4])
                                   : make_float4(1e30f, 1e30f, 1e30f, 1e30f);
            }

            float lmin = 1e30f;
            int lq = QQ;
#pragma unroll
            for (int s = 0; s < 4; s++) {
                int f4 = tid + (s << 6);
                if (f4 < NF4) {
                    int q0 = f4 << 2;
                    float4 v4 = *(const float4*)&sv[q0];
                    float4 m4 = *(const float4*)&sminv[q0];
                    float cur;
                    cur = c4[s].x - ueff - v4.x;
                    if (cur < m4.x) { m4.x = cur; sway[q0] = j0; }       // false if NaN
                    cur = c4[s].y - ueff - v4.y;
                    if (cur < m4.y) { m4.y = cur; sway[q0 + 1] = j0; }
                    cur = c4[s].z - ueff - v4.z;
                    if (cur < m4.z) { m4.z = cur; sway[q0 + 2] = j0; }
                    cur = c4[s].w - ueff - v4.w;
                    if (cur < m4.w) { m4.w = cur; sway[q0 + 3] = j0; }
                    *(float4*)&sminv[q0] = m4;
                    if (m4.x < lmin) { lmin = m4.x; lq = q0; }           // NaN excluded
                    if (m4.y < lmin) { lmin = m4.y; lq = q0 + 1; }
                    if (m4.z < lmin) { lmin = m4.z; lq = q0 + 2; }
                    if (m4.w < lmin) { lmin = m4.w; lq = q0 + 3; }
                }
            }
            // per-warp argmin via hardware reduces, then cross-warp packed min
            unsigned int key = fkey(lmin);
            unsigned int mkey = __reduce_min_sync(0xffffffffu, key);
            unsigned int qsel = (key == mkey) ? (unsigned int)lq : 0xffffffffu;
            unsigned int qmin = __reduce_min_sync(0xffffffffu, qsel);
            if (lane == 0)
                swcomb[wid] = ((unsigned long long)mkey << 32) | qmin;
            __syncthreads();
            unsigned long long comb = min(swcomb[0], swcomb[1]);
            __syncthreads();   // protect swcomb reuse next phase
            D = fkey_inv((unsigned int)(comb >> 32));  // bit-identical to winner
            j0 = (int)(comb & 0xFFFFFFFFull);
            int pj = sp[j0];
            if (pj < 0) break;
            i0 = pj;
        }

        // commit duals over used columns (distinct rows & cols -> race-free)
        for (int t = tid; t < cnt; t += 64) {
            int j = susedList[t];
            float dd = D - sDused[t];
            if (j < 0) su[f] += dd;
            else { su[sp[j]] += dd; sv[j] -= dd; }
        }
        __syncthreads();
        if (tid == 0) {
            int jj = j0;
            while (jj >= 0) {
                int jn = sway[jj];
                sp[jj] = (jn < 0) ? f : sp[jn];
                jj = jn;
            }
        }
        __syncthreads();
    }

    for (int q = tid; q < QQ; q += 64) {
        int r = sp[q];
        g_match[b * QQ + q] = (r >= 0) ? g_vlist[b * GG + r] : -1;
    }
    if (tid == 0) atomicAdd(&g_nmatched, n);
}

__global__ void loss_kernel(const float* __restrict__ logits,
                            const float* __restrict__ pboxes,
                            const int*   __restrict__ gtc,
                            const float* __restrict__ gboxes,
                            float* __restrict__ out) {
    int idx = blockIdx.x * blockDim.x + threadIdx.x;
    double nllw = 0.0, wsum = 0.0, l1acc = 0.0, glacc = 0.0;

    if (idx < BB * QQ) {
        int b = idx / QQ;
        int mg = g_match[idx];
        int t = (mg >= 0) ? gtc[b * GG + mg] : NC;
        float logp = logits[(size_t)idx * NC1 + t] - g_logZ[idx];
        float wt = (t == NC) ? 0.1f : 1.0f;
        nllw = (double)(wt * (-logp));
        wsum = (double)wt;

        if (mg >= 0) {
            const float* pb = pboxes + (size_t)idx * 4;
            const float* gb = gboxes + ((size_t)(b * GG + mg)) * 4;
            float pcx = pb[0], pcy = pb[1], pw = pb[2], ph = pb[3];
            float gcx = gb[0], gcy = gb[1], gw = gb[2], gh = gb[3];
            l1acc = (double)(fabsf(pcx - gcx) + fabsf(pcy - gcy) +
                             fabsf(pw - gw) + fabsf(ph - gh));
            float px0 = pcx - pw * 0.5f, py0 = pcy - ph * 0.5f;
            float px1 = pcx + pw * 0.5f, py1 = pcy + ph * 0.5f;
            float gx0 = gcx - gw * 0.5f, gy0 = gcy - gh * 0.5f;
            float gx1 = gcx + gw * 0.5f, gy1 = gcy + gh * 0.5f;
            float pa = fmaxf(px1 - px0, 0.f) * fmaxf(py1 - py0, 0.f);
            float ga = fmaxf(gx1 - gx0, 0.f) * fmaxf(gy1 - gy0, 0.f);
            float ltx = fmaxf(px0, gx0), lty = fmaxf(py0, gy0);
            float rbx = fminf(px1, gx1), rby = fminf(py1, gy1);
            float iw = fmaxf(rbx - ltx, 0.f), ih = fmaxf(rby - lty, 0.f);
            float inter = iw * ih;
            float uni = pa + ga - inter;
            float iou = inter / fmaxf(uni, 1e-6f);
            float ex0 = fminf(px0, gx0), ey0 = fminf(py0, gy0);
            float ex1 = fmaxf(px1, gx1), ey1 = fmaxf(py1, gy1);
            float ew = fmaxf(ex1 - ex0, 0.f), eh = fmaxf(ey1 - ey0, 0.f);
            float enc = ew * eh;
            float giou = iou - (enc - uni) / fmaxf(enc, 1e-6f);
            glacc = (double)(1.0f - giou);
        }
    }

    __shared__ double s1[256], s2[256], s3[256], s4[256];
    int tid = threadIdx.x;
    s1[tid] = nllw; s2[tid] = wsum; s3[tid] = l1acc; s4[tid] = glacc;
    __syncthreads();
#pragma unroll
    for (int s = 128; s > 0; s >>= 1) {
        if (tid < s) {
            s1[tid] += s1[tid + s];
            s2[tid] += s2[tid + s];
            s3[tid] += s3[tid + s];
            s4[tid] += s4[tid + s];
        }
        __syncthreads();
    }
    if (tid == 0) {
        atomicAdd(&g_cls_num, s1[0]);
        atomicAdd(&g_cls_den, s2[0]);
        atomicAdd(&g_l1, s3[0]);
        atomicAdd(&g_gl, s4[0]);
        __threadfence();
        int done = atomicAdd(&g_loss_done, 1);
        if (done == gridDim.x - 1) {   // last block finalizes
            int nm = g_nmatched;
            if (nm < 1) nm = 1;
            double nmd = (double)nm;
            double cls = g_cls_num / g_cls_den;
            out[0] = (float)(2.0 * cls + 5.0 * g_l1 / nmd + 2.0 * g_gl / nmd);
        }
    }
}

extern "C" void kernel_launch(void* const* d_in, const int* in_sizes, int n_in,
                              void* d_out, int out_size) {
    const float* pred_logits = (const float*)d_in[0];
    const float* pred_boxes  = (const float*)d_in[1];
    const int*   gt_classes  = (const int*)d_in[2];
    const float* gt_boxes    = (const float*)d_in[3];
    float* out = (float*)d_out;

    prep_kernel<<<BB, 128>>>(gt_classes);

    dim3 cgrid((QQ + 127) / 128, BB, (GG + KCHUNK - 1) / KCHUNK);
    cost_kernel<<<cgrid, 128>>>(pred_logits, pred_boxes, gt_classes, gt_boxes);

    jv_kernel<<<BB, 64>>>();

    int total = BB * QQ;
    loss_kernel<<<(total + 255) / 256, 256>>>(pred_logits, pred_boxes,
                                              gt_classes, gt_boxes, out);
}